// round 13
// baseline (speedup 1.0000x reference)
#include <cuda_runtime.h>
#include <cuda_bf16.h>
#include <cstdint>

// NCE loss (training branch, size_average=True).
// N=4096, E=1024, V=50257, K=25.
// Persistent kernel: 1184 CTAs (8/SM x 148 SMs) grid-striding over rows.
// Converged design: this problem is LTS-capped (~452MB of irreducible fp32
// weight-gather traffic through L2 fabric ~ 6300 B/cyc => ~57us floor).
// Mainloop: 8 warps x 3-4 dots/row, 8 independent LDG.128 per lane (__ldg).
// x rows stream through a 3-slot cp.async SMEM ring -> ONE barrier per row
// (reuse distance 3 makes the trailing barrier redundant).
// Epilogue: one float atomicAdd per CTA into d_out (zeroed by memset node).

#define THREADS 256
#define NWARP   8
#define GRID    1184          // 148 SMs * 8 CTAs
#define XBUF    3

__device__ __forceinline__ void cp16(uint32_t dst, const void* src) {
    asm volatile("cp.async.cg.shared.global [%0], [%1], 16;\n" :: "r"(dst), "l"(src));
}
__device__ __forceinline__ void cp_commit() {
    asm volatile("cp.async.commit_group;\n" ::: "memory");
}

__global__ __launch_bounds__(THREADS, 8)
void nce_main(const float* __restrict__ x,
              const int*   __restrict__ target,
              const int*   __restrict__ noise_idx,
              const float* __restrict__ weight,
              const float* __restrict__ bias,
              const float* __restrict__ noise,
              float* __restrict__ out,
              int N, int E, int K)
{
    const int tid  = threadIdx.x;
    const int lane = tid & 31;
    const int wid  = tid >> 5;
    const int nk   = K + 1;                // 26

    __shared__ float4 xs[XBUF][256];       // 3-slot x-row ring (12KB)
    __shared__ float  wloss[NWARP];

    uint32_t xs_addr[XBUF];
    {
        uint32_t base;
        asm("{ .reg .u64 t; cvta.to.shared.u64 t, %1; cvt.u32.u64 %0, t; }"
            : "=r"(base) : "l"(&xs[0][0]));
        #pragma unroll
        for (int b = 0; b < XBUF; b++) xs_addr[b] = base + b * 4096 + tid * 16;
    }

    // Prime slot 0 with the first row's x
    const int n0 = blockIdx.x;
    if (n0 < N) {
        cp16(xs_addr[0], (const char*)(x + (size_t)n0 * E) + tid * 16);
        cp_commit();
    }

    float loss = 0.0f;                     // lane-0-held across rows
    int buf = 0;

    for (int n = n0; n < N; n += GRID) {
        // Stream the NEXT row's x into the next ring slot. The slot being
        // overwritten was consumed two barriers ago (reuse distance 3), so
        // no trailing barrier is needed.
        const int n_next = n + GRID;
        const int nbuf   = (buf + 1 == XBUF) ? 0 : buf + 1;
        if (n_next < N) {
            cp16(xs_addr[nbuf], (const char*)(x + (size_t)n_next * E) + tid * 16);
            cp_commit();
            asm volatile("cp.async.wait_group 1;\n" ::: "memory");  // this row in
        } else {
            asm volatile("cp.async.wait_group 0;\n" ::: "memory");
        }
        __syncthreads();                   // single barrier per row

        const float4* xb = xs[buf];

        for (int k = wid; k < nk; k += NWARP) {
            const int idx = (k == 0) ? target[n] : noise_idx[n * K + (k - 1)];
            const float4* wrow = reinterpret_cast<const float4*>(weight + (size_t)idx * E);

            float s = 0.0f;
            #pragma unroll
            for (int j = 0; j < 8; j++) {   // 8 independent LDG.128 per lane
                const float4 wv = __ldg(&wrow[lane + 32 * j]);
                const float4 xv = xb[lane + 32 * j];
                s += wv.x * xv.x + wv.y * xv.y + wv.z * xv.z + wv.w * xv.w;
            }
            #pragma unroll
            for (int o = 16; o; o >>= 1)
                s += __shfl_xor_sync(0xffffffffu, s, o);

            if (lane == 0) {
                const float logit = s + __ldg(&bias[idx]);
                const float p     = __expf(logit - 9.0f);
                const float kpn   = 25.0f * __ldg(&noise[idx]);
                const float num   = (k == 0) ? p : kpn;
                loss += __logf(num / (p + kpn));
            }
        }
        buf = nbuf;
    }

    if (lane == 0) wloss[wid] = loss;
    __syncthreads();
    if (tid == 0) {
        float t = 0.0f;
        #pragma unroll
        for (int w = 0; w < NWARP; w++) t += wloss[w];
        atomicAdd(out, -t / (float)N);     // one atomic per CTA
    }
}

extern "C" void kernel_launch(void* const* d_in, const int* in_sizes, int n_in,
                              void* d_out, int out_size)
{
    const float* x         = (const float*)d_in[0];
    const int*   target    = (const int*)  d_in[1];
    const int*   noise_idx = (const int*)  d_in[2];
    const float* weight    = (const float*)d_in[3];
    const float* bias      = (const float*)d_in[4];
    const float* noise     = (const float*)d_in[5];

    const int N = in_sizes[1];            // 4096
    const int E = in_sizes[0] / N;        // 1024
    const int K = in_sizes[2] / N;        // 25

    cudaMemsetAsync(d_out, 0, sizeof(float));
    nce_main<<<GRID, THREADS>>>(x, target, noise_idx, weight, bias, noise,
                                (float*)d_out, N, E, K);
}

// round 14
// speedup vs baseline: 1.0016x; 1.0016x over previous
#include <cuda_runtime.h>
#include <cuda_bf16.h>
#include <cstdint>

// NCE loss (training branch, size_average=True).  CONVERGED KERNEL (R7 config,
// best of 13 measured variants at 57.4us).
// N=4096, E=1024, V=50257, K=25.
//
// Why this shape: the problem is bound by the irreducible ~436MB random fp32
// weight-row gather (4096 rows x 26 candidates x 4KB) flowing through
// L1tex/LTS. 13 structurally different schedules (occupancy 36-90%, DRAM
// bytes 231-302MB, 0-2 barriers/row, cp.async weight staging, two-pass L2
// blocking, warp-autonomous flattening) all land at 57-62us -> this is the
// gather-equilibrium floor, and the config below measured fastest.
//
// Design: persistent grid of 1184 CTAs (8/SM x 148 SMs, 64 warps/SM = HW max),
// 256 thr / 32 regs. Each CTA grid-strides rows; per row 8 warps handle the
// 26 dot products (8 independent LDG.128 per lane, warp-shfl reduce). x rows
// are double-buffered in SMEM via cp.async so the next row's x streams behind
// the current row's dots. Epilogue: one float atomicAdd per CTA into d_out
// (zeroed each replay by a memset node).

#define THREADS 256
#define NWARP   8
#define GRID    1184          // 148 SMs * 8 CTAs

__device__ __forceinline__ void cp16(uint32_t dst, const void* src) {
    asm volatile("cp.async.cg.shared.global [%0], [%1], 16;\n" :: "r"(dst), "l"(src));
}
__device__ __forceinline__ void cp_commit() {
    asm volatile("cp.async.commit_group;\n" ::: "memory");
}

__global__ __launch_bounds__(THREADS, 8)
void nce_main(const float* __restrict__ x,
              const int*   __restrict__ target,
              const int*   __restrict__ noise_idx,
              const float* __restrict__ weight,
              const float* __restrict__ bias,
              const float* __restrict__ noise,
              float* __restrict__ out,
              int N, int E, int K)
{
    const int tid  = threadIdx.x;
    const int lane = tid & 31;
    const int wid  = tid >> 5;
    const int nk   = K + 1;                // 26

    __shared__ float4 xs[2][256];          // double-buffered x row
    __shared__ float  wloss[NWARP];

    uint32_t xs_addr[2];
    {
        uint32_t base;
        asm("{ .reg .u64 t; cvta.to.shared.u64 t, %1; cvt.u32.u64 %0, t; }"
            : "=r"(base) : "l"(&xs[0][0]));
        xs_addr[0] = base + tid * 16;
        xs_addr[1] = base + 4096 + tid * 16;
    }

    // Prime buffer 0 with the first row's x
    const int n0 = blockIdx.x;
    if (n0 < N) {
        cp16(xs_addr[0], (const char*)(x + (size_t)n0 * E) + tid * 16);
        cp_commit();
    }

    float loss = 0.0f;                     // lane-0-held across rows
    int buf = 0;

    for (int n = n0; n < N; n += GRID, buf ^= 1) {
        // Start streaming the NEXT row's x into the other buffer
        const int n_next = n + GRID;
        if (n_next < N) {
            cp16(xs_addr[buf ^ 1], (const char*)(x + (size_t)n_next * E) + tid * 16);
            cp_commit();
            asm volatile("cp.async.wait_group 1;\n" ::: "memory");  // this row in
        } else {
            asm volatile("cp.async.wait_group 0;\n" ::: "memory");
        }
        __syncthreads();

        const float4* xb = xs[buf];

        for (int k = wid; k < nk; k += NWARP) {
            const int idx = (k == 0) ? target[n] : noise_idx[n * K + (k - 1)];
            const float4* wrow = reinterpret_cast<const float4*>(weight + (size_t)idx * E);

            float s = 0.0f;
            #pragma unroll
            for (int j = 0; j < 8; j++) {   // 8 independent LDG.128 per lane
                const float4 wv = __ldg(&wrow[lane + 32 * j]);
                const float4 xv = xb[lane + 32 * j];
                s += wv.x * xv.x + wv.y * xv.y + wv.z * xv.z + wv.w * xv.w;
            }
            #pragma unroll
            for (int o = 16; o; o >>= 1)
                s += __shfl_xor_sync(0xffffffffu, s, o);

            if (lane == 0) {
                const float logit = s + __ldg(&bias[idx]);
                const float p     = __expf(logit - 9.0f);
                const float kpn   = 25.0f * __ldg(&noise[idx]);
                const float num   = (k == 0) ? p : kpn;
                loss += __logf(num / (p + kpn));
            }
        }
        __syncthreads();   // xs[buf] fully consumed before refill
    }

    if (lane == 0) wloss[wid] = loss;
    __syncthreads();
    if (tid == 0) {
        float t = 0.0f;
        #pragma unroll
        for (int w = 0; w < NWARP; w++) t += wloss[w];
        atomicAdd(out, -t / (float)N);     // one atomic per CTA
    }
}

extern "C" void kernel_launch(void* const* d_in, const int* in_sizes, int n_in,
                              void* d_out, int out_size)
{
    const float* x         = (const float*)d_in[0];
    const int*   target    = (const int*)  d_in[1];
    const int*   noise_idx = (const int*)  d_in[2];
    const float* weight    = (const float*)d_in[3];
    const float* bias      = (const float*)d_in[4];
    const float* noise     = (const float*)d_in[5];

    const int N = in_sizes[1];            // 4096
    const int E = in_sizes[0] / N;        // 1024
    const int K = in_sizes[2] / N;        // 25

    cudaMemsetAsync(d_out, 0, sizeof(float));
    nce_main<<<GRID, THREADS>>>(x, target, noise_idx, weight, bias, noise,
                                (float*)d_out, N, E, K);
}